// round 15
// baseline (speedup 1.0000x reference)
#include <cuda_runtime.h>

// Problem constants
#define B_TOT  2
#define E_TOT  2048
#define N1_TOT 96
#define K_TOT  32
#define CIN    64
#define CB     32
#define COUT   64
#define WCNT   (160*COUT)     // 10240 floats per W_eq group
#define NEG_SLOPE 0.01f

#define NPB    16             // bond feature pairs (CB/2)
#define EPW    4              // edges per warp
#define EPC    32             // edges per CTA
#define GRID_M 128            // 4096/32

#define CTOP_ROWS 192         // B*N1
#define PREP_CTAS 16          // 16 rows each; 16+128 <= 148 -> full co-residency
#define RPP       16          // rows per prep CTA

// fma on packed f32x2 (feature pairs)
#define FMA2(acc, v, wgt) \
    asm("fma.rn.f32x2 %0, %1, %2, %0;" : "+l"(acc) : "l"(v), "l"(wgt))

// Prep outputs:
//   g_ctop[(b*96+n1)*64 + o] = s1[b,n1,:] . Wbar[0:64, o]
//   g_cmid[(b*32+k )*64 + o] = s2[b,k ,:] . Wbar[64:128, o] + b_eq[o]
__device__ float g_ctop[CTOP_ROWS * COUT];
__device__ float g_cmid[B_TOT * K_TOT * COUT];

// ---------------------------------------------------------------------------
// Prep: 16 CTAs x 256 threads. CTA p computes rows 16p..16p+15 of the 256
// combined (ctop|cmid) rows: stages its averaged 64-row W panel (16 KB,
// coalesced float4) + 16 s rows, then 4 dots of 64 MACs per thread.
// Also zeroes d_out (256 elems per CTA). PDL trigger at start.
// ---------------------------------------------------------------------------
__global__ void __launch_bounds__(256, 1) prep_kernel(
    const float* __restrict__ sites1,
    const float* __restrict__ sites2,
    const float* __restrict__ W_eq,
    const float* __restrict__ b_eq,
    float* __restrict__ out)
{
#if __CUDA_ARCH__ >= 900
    cudaTriggerProgrammaticLaunchCompletion();
#endif
    __shared__ float Wavg_sh[64 * COUT];   // 16384 B
    __shared__ float s_sh[RPP * CIN];      //  4096 B

    const int tid = threadIdx.x;
    const int p   = blockIdx.x;
    const bool is_top = (p < 12);          // 12*16 = 192 ctop rows

    // Stage averaged W panel (rows [0,64) or [64,128)): 1024 float4.
    {
        const int base4 = (is_top ? 0 : CIN) * (COUT / 4);
        const float4* g0 = (const float4*)W_eq + base4;
        const float4* g1 = (const float4*)(W_eq + WCNT) + base4;
        const float4* g2 = (const float4*)(W_eq + 2 * WCNT) + base4;
        const float4* g3 = (const float4*)(W_eq + 3 * WCNT) + base4;
        float4* dst = (float4*)Wavg_sh;
        #pragma unroll
        for (int j = 0; j < 4; j++) {
            const int i = tid + j * 256;
            const float4 a = g0[i], b4 = g1[i], cc = g2[i], d = g3[i];
            float4 r;
            r.x = 0.25f * (a.x + b4.x + cc.x + d.x);
            r.y = 0.25f * (a.y + b4.y + cc.y + d.y);
            r.z = 0.25f * (a.z + b4.z + cc.z + d.z);
            r.w = 0.25f * (a.w + b4.w + cc.w + d.w);
            dst[i] = r;
        }
    }
    // Stage 16 s rows (1024 floats, coalesced).
    #pragma unroll
    for (int j = 0; j < 4; j++) {
        const int i   = tid + j * 256;
        const int row = i >> 6;                  // 0..15
        const int o   = i & 63;
        const int R   = RPP * p + row;           // global row 0..255
        s_sh[i] = is_top ? sites1[R * CIN + o]
                         : sites2[(R - CTOP_ROWS) * CIN + o];
    }
    // Zero out slice (16 CTAs x 256 = 4096).
    out[p * 256 + tid] = 0.0f;
    __syncthreads();

    // 4 dots per thread (64 MACs each).
    #pragma unroll
    for (int j = 0; j < 4; j++) {
        const int i   = tid + j * 256;
        const int row = i >> 6;
        const int o   = i & 63;
        const int R   = RPP * p + row;
        float acc = 0.0f;
        #pragma unroll 16
        for (int f = 0; f < CIN; f++)
            acc += s_sh[row * CIN + f] * Wavg_sh[f * COUT + o];
        if (is_top) g_ctop[R * COUT + o] = acc;
        else        g_cmid[(R - CTOP_ROWS) * COUT + o] = acc + b_eq[o];
    }
}

// ---------------------------------------------------------------------------
// Main: 128 CTAs x 256 threads (8 warps). Warp owns 4 edges.
// Pre-sync (overlaps prep): bonds gather, Wbot avg+permute, bonds FMA loop.
// Post-sync: ctop/cmid prefetch, combine, activation, attention, scatter.
// Thread t owns outputs {t, t+32}.
// ---------------------------------------------------------------------------
__global__ void __launch_bounds__(256, 1) main_kernel(
    const float* __restrict__ bonds,
    const float* __restrict__ W_eq,
    const float* __restrict__ W_att,
    const float* __restrict__ b_att,
    const int*   __restrict__ idx1,
    const int*   __restrict__ idx2,
    float* __restrict__ out)
{
    __shared__ float Wraw_sh[CB * COUT];   // averaged Wbot raw [f][o] (8192 B)
    __shared__ float Wbot_sh[CB * COUT];   // paired layout (8192 B)
    __shared__ float vsh[EPC * CB];        // bonds (4096 B)

    const int tid  = threadIdx.x;
    const int lane = tid & 31;
    const int w    = tid >> 5;
    const int c    = blockIdx.x;

    // ---- Pre-sync 1: bonds gather + edge metadata ----
    int ctop_off[EPW], cmid_off[EPW];
    #pragma unroll
    for (int j = 0; j < EPW; j++) {
        const int le = w * EPW + j;
        const int ei = c * EPC + le;
        const int b  = ei >> 11;
        const int e  = ei & (E_TOT - 1);
        const int i1 = idx1[e];
        const int i2 = idx2[e];
        ctop_off[j] = (b * N1_TOT + i1) * COUT;
        cmid_off[j] = (b * K_TOT  + i2) * COUT;
        vsh[le * CB + lane] = bonds[(b * E_TOT + e) * CB + lane];
    }
    const float waT = W_att[lane];
    const float waU = W_att[lane + 32];
    const float ba  = b_att[0];

    // ---- Pre-sync 2: averaged Wbot (rows 128..159, contiguous) ----
    {
        const float4* g0 = (const float4*)(W_eq + 128 * COUT);
        const float4* g1 = (const float4*)(W_eq + WCNT + 128 * COUT);
        const float4* g2 = (const float4*)(W_eq + 2 * WCNT + 128 * COUT);
        const float4* g3 = (const float4*)(W_eq + 3 * WCNT + 128 * COUT);
        float4* dst = (float4*)Wraw_sh;
        #pragma unroll
        for (int j = 0; j < 2; j++) {
            const int i = tid + j * 256;
            const float4 a = g0[i], b4 = g1[i], cc = g2[i], d = g3[i];
            float4 r;
            r.x = 0.25f * (a.x + b4.x + cc.x + d.x);
            r.y = 0.25f * (a.y + b4.y + cc.y + d.y);
            r.z = 0.25f * (a.z + b4.z + cc.z + d.z);
            r.w = 0.25f * (a.w + b4.w + cc.w + d.w);
            dst[i] = r;
        }
    }
    __syncthreads();
    // Permute to paired layout in smem:
    // paired[ip*128 + t*4 + sl] = raw[(2ip + (sl&1))*64 + t + 32*(sl>>1)]
    #pragma unroll
    for (int j = 0; j < 8; j++) {
        const int i  = tid + j * 256;            // 0..2047
        const int ip = i >> 7, rr = i & 127, t = rr >> 2, sl = rr & 3;
        Wbot_sh[i] = Wraw_sh[(2 * ip + (sl & 1)) * COUT + t + 32 * (sl >> 1)];
    }
    __syncthreads();

    // ---- Pre-sync 3: bonds FMA loop (16 f-pair iters x 4 edges) ----
    const ulonglong2* Wq = (const ulonglong2*)Wbot_sh;
    const float* vb = vsh + (w * EPW) * CB;

    unsigned long long aT[EPW], aU[EPW];
    #pragma unroll
    for (int j = 0; j < EPW; j++) { aT[j] = 0ull; aU[j] = 0ull; }

    #pragma unroll
    for (int ip = 0; ip < NPB; ip++) {
        const ulonglong2 wq = Wq[ip * 32 + lane];
        #pragma unroll
        for (int j = 0; j < EPW; j++) {
            const unsigned long long vp =
                *(const unsigned long long*)(vb + j * CB + 2 * ip);  // broadcast
            FMA2(aT[j], vp, wq.x);
            FMA2(aU[j], vp, wq.y);
        }
    }

    // ---- Wait for prep (ctop/cmid ready, out zeroed) ----
#if __CUDA_ARCH__ >= 900
    cudaGridDependencySynchronize();
#endif

    // ---- Post-sync: combine + epilogue ----
    #pragma unroll
    for (int j = 0; j < EPW; j++) {
        const float ctT = g_ctop[ctop_off[j] + lane];
        const float ctU = g_ctop[ctop_off[j] + lane + 32];
        const float cmT = g_cmid[cmid_off[j] + lane];
        const float cmU = g_cmid[cmid_off[j] + lane + 32];

        float yT = __uint_as_float((unsigned)(aT[j] & 0xffffffffull))
                 + __uint_as_float((unsigned)(aT[j] >> 32)) + ctT + cmT;
        float yU = __uint_as_float((unsigned)(aU[j] & 0xffffffffull))
                 + __uint_as_float((unsigned)(aU[j] >> 32)) + ctU + cmU;
        yT = (yT > 0.0f) ? yT : NEG_SLOPE * yT;
        yU = (yU > 0.0f) ? yU : NEG_SLOPE * yU;

        float p = yT * waT + yU * waU;
        #pragma unroll
        for (int s = 16; s > 0; s >>= 1)
            p += __shfl_xor_sync(0xffffffffu, p, s);
        const float att = 1.0f / (1.0f + __expf(-(p + ba)));

        float* dst = out + cmid_off[j];   // (b*K + i2)*COUT
        atomicAdd(dst + lane,      att * yT);
        atomicAdd(dst + lane + 32, att * yU);
    }
}

// ---------------------------------------------------------------------------
extern "C" void kernel_launch(void* const* d_in, const int* in_sizes, int n_in,
                              void* d_out, int out_size)
{
    const float* sites1 = (const float*)d_in[0];
    const float* sites2 = (const float*)d_in[1];
    const float* bonds  = (const float*)d_in[2];
    const float* W_eq   = (const float*)d_in[3];
    const float* b_eq   = (const float*)d_in[4];
    const float* W_att  = (const float*)d_in[5];
    const float* b_att  = (const float*)d_in[6];
    // d_in[7] = idx2_oh (unused — collapsed analytically)
    const int*   idx1   = (const int*)d_in[8];
    const int*   idx2   = (const int*)d_in[9];
    // d_in[10], d_in[11] = perms1/perms2 (unused — permutations cancel)
    float* out = (float*)d_out;

    // prep: 16 CTAs (16+128 = 144 <= 148 SMs -> full co-residency under PDL)
    {
        cudaLaunchConfig_t cfg = {};
        cfg.gridDim  = dim3(PREP_CTAS);
        cfg.blockDim = dim3(256);
        cfg.stream = 0;
        cudaLaunchKernelEx(&cfg, prep_kernel, sites1, sites2, W_eq, b_eq, out);
    }

    // main with programmatic dependent launch (everything pre-sync overlaps prep)
    {
        cudaLaunchConfig_t cfg = {};
        cfg.gridDim  = dim3(GRID_M);
        cfg.blockDim = dim3(256);
        cfg.stream = 0;
        cudaLaunchAttribute at[1];
        at[0].id = cudaLaunchAttributeProgrammaticStreamSerialization;
        at[0].val.programmaticStreamSerializationAllowed = 1;
        cfg.attrs = at;
        cfg.numAttrs = 1;
        cudaLaunchKernelEx(&cfg, main_kernel, bonds, W_eq, W_att, b_att,
                           idx1, idx2, out);
    }
}

// round 16
// speedup vs baseline: 1.2286x; 1.2286x over previous
#include <cuda_runtime.h>

// Problem constants
#define B_TOT  2
#define E_TOT  2048
#define N1_TOT 96
#define K_TOT  32
#define CIN    64
#define CB     32
#define COUT   64
#define WCNT   (160*COUT)     // 10240 floats per W_eq group
#define NEG_SLOPE 0.01f

#define NPB    16             // bond feature pairs (CB/2)
#define WBOT_CNT (CB*COUT)    // 2048 floats
#define EPW    4
#define EPC    32             // edges per CTA
#define GRID_M 128            // 4096/32

#define CTOP_ROWS 192         // B*N1
#define PREP_CTAS 64          // 4 rows each: 48 top + 16 mid

// fma on packed f32x2 (feature pairs)
#define FMA2(acc, v, wgt) \
    asm("fma.rn.f32x2 %0, %1, %2, %0;" : "+l"(acc) : "l"(v), "l"(wgt))

// Prep outputs:
//   g_ctop[(b*96+n1)*64 + o] = s1[b,n1,:] . Wbar[0:64, o]
//   g_cmid[(b*32+k )*64 + o] = s2[b,k ,:] . Wbar[64:128, o] + b_eq[o]
//   g_WbotP: Wbar rows 128..159 in paired layout for main's LDS.128:
//     float i = ip*128 + t*4 + sl -> Wbot[f=2*ip+(sl&1)][o=t+32*(sl>>1)]
__device__ float g_ctop[CTOP_ROWS * COUT];
__device__ float g_cmid[B_TOT * K_TOT * COUT];
__device__ float g_WbotP[WBOT_CNT];

// ---------------------------------------------------------------------------
// Prep: 64 CTAs x 256 threads, 4 rows per CTA (critical-path optimized).
//  - stage 16KB averaged half-panel (coalesced float4, L2-hot)
//  - 4 s rows, one 64-MAC dot per thread
//  - zero 64 outs per CTA
//  - CTA 0 only: Wbot coalesced average -> smem permute -> g_WbotP
// ---------------------------------------------------------------------------
__global__ void __launch_bounds__(256, 1) prep_kernel(
    const float* __restrict__ sites1,
    const float* __restrict__ sites2,
    const float* __restrict__ W_eq,
    const float* __restrict__ b_eq,
    float* __restrict__ out)
{
#if __CUDA_ARCH__ >= 900
    cudaTriggerProgrammaticLaunchCompletion();
#endif
    __shared__ float Wavg_sh[CIN * COUT];   // 16384 B
    __shared__ float s_sh[4 * CIN];         //  1024 B
    __shared__ float Wraw_sh[WBOT_CNT];     //  8192 B (CTA 0 only)

    const int tid = threadIdx.x;
    const int p   = blockIdx.x;
    const bool is_top = (p < 48);           // 48*4 = 192 ctop rows

    // Averaged half-panel: W rows [0,64) or [64,128), 1024 float4.
    {
        const int base4 = (is_top ? 0 : CIN) * (COUT / 4);
        const float4* g0 = (const float4*)W_eq + base4;
        const float4* g1 = (const float4*)(W_eq + WCNT) + base4;
        const float4* g2 = (const float4*)(W_eq + 2 * WCNT) + base4;
        const float4* g3 = (const float4*)(W_eq + 3 * WCNT) + base4;
        float4* dst = (float4*)Wavg_sh;
        #pragma unroll
        for (int j = 0; j < 4; j++) {
            const int i = tid + j * 256;
            const float4 a = g0[i], b4 = g1[i], cc = g2[i], d = g3[i];
            float4 r;
            r.x = 0.25f * (a.x + b4.x + cc.x + d.x);
            r.y = 0.25f * (a.y + b4.y + cc.y + d.y);
            r.z = 0.25f * (a.z + b4.z + cc.z + d.z);
            r.w = 0.25f * (a.w + b4.w + cc.w + d.w);
            dst[i] = r;
        }
    }
    // 4 s rows (256 floats, one per thread, coalesced).
    {
        const int row = tid >> 6;               // 0..3
        const int o   = tid & 63;
        const int R   = 4 * p + row;            // global row 0..255
        s_sh[tid] = is_top ? sites1[R * CIN + o]
                           : sites2[(R - CTOP_ROWS) * CIN + o];
    }
    // Zero out slice (64 CTAs x 64 = 4096).
    if (tid < 64) out[p * 64 + tid] = 0.0f;

    // CTA 0: averaged Wbot raw (rows 128..159 contiguous, 512 float4).
    if (p == 0) {
        const float4* g0 = (const float4*)(W_eq + 128 * COUT);
        const float4* g1 = (const float4*)(W_eq + WCNT + 128 * COUT);
        const float4* g2 = (const float4*)(W_eq + 2 * WCNT + 128 * COUT);
        const float4* g3 = (const float4*)(W_eq + 3 * WCNT + 128 * COUT);
        float4* dst = (float4*)Wraw_sh;
        #pragma unroll
        for (int j = 0; j < 2; j++) {
            const int i = tid + j * 256;
            const float4 a = g0[i], b4 = g1[i], cc = g2[i], d = g3[i];
            float4 r;
            r.x = 0.25f * (a.x + b4.x + cc.x + d.x);
            r.y = 0.25f * (a.y + b4.y + cc.y + d.y);
            r.z = 0.25f * (a.z + b4.z + cc.z + d.z);
            r.w = 0.25f * (a.w + b4.w + cc.w + d.w);
            dst[i] = r;
        }
    }
    __syncthreads();

    // One 64-MAC dot per thread (s broadcast per warp, conflict-free W).
    {
        const int row = tid >> 6;
        const int o   = tid & 63;
        const int R   = 4 * p + row;
        float acc = 0.0f;
        #pragma unroll 16
        for (int f = 0; f < CIN; f++)
            acc += s_sh[row * CIN + f] * Wavg_sh[f * COUT + o];
        if (is_top) g_ctop[R * COUT + o] = acc;
        else        g_cmid[(R - CTOP_ROWS) * COUT + o] = acc + b_eq[o];
    }

    // CTA 0: permute raw -> paired, write g_WbotP (coalesced STG).
    if (p == 0) {
        #pragma unroll
        for (int j = 0; j < 8; j++) {
            const int i  = tid + j * 256;       // 0..2047
            const int ip = i >> 7, rr = i & 127, t = rr >> 2, sl = rr & 3;
            g_WbotP[i] = Wraw_sh[(2 * ip + (sl & 1)) * COUT + t + 32 * (sl >> 1)];
        }
    }
}

// ---------------------------------------------------------------------------
// Main (R10's proven 6.2us kernel, verbatim): 128 CTAs x 256 threads.
// Warp owns 4 edges; lat = c_top + c_mid(+b_eq) + bonds.W_bot; 16-iter loop.
// Thread t owns outputs {t, t+32}.
// ---------------------------------------------------------------------------
__global__ void __launch_bounds__(256, 1) main_kernel(
    const float* __restrict__ bonds,
    const float* __restrict__ W_att,
    const float* __restrict__ b_att,
    const int*   __restrict__ idx1,
    const int*   __restrict__ idx2,
    float* __restrict__ out)
{
    __shared__ float Wsh[WBOT_CNT];          // 8192 B
    __shared__ float vsh[EPC * CB];          // 4096 B

    const int tid  = threadIdx.x;
    const int lane = tid & 31;
    const int w    = tid >> 5;

    // ---- Phase A: bonds gather + metadata (independent of prep) ----
    int ctop_off[EPW], cmid_off[EPW];
    #pragma unroll
    for (int j = 0; j < EPW; j++) {
        const int le = w * EPW + j;
        const int ei = blockIdx.x * EPC + le;
        const int b  = ei >> 11;
        const int e  = ei & (E_TOT - 1);
        const int i1 = idx1[e];    // broadcast load
        const int i2 = idx2[e];
        ctop_off[j] = (b * N1_TOT + i1) * COUT;
        cmid_off[j] = (b * K_TOT  + i2) * COUT;
        vsh[le * CB + lane] = bonds[(b * E_TOT + e) * CB + lane];
    }
    const float waT = W_att[lane];
    const float waU = W_att[lane + 32];
    const float ba  = b_att[0];

    // ---- Wait for prep outputs (ctop/cmid/WbotP/out-zero) ----
#if __CUDA_ARCH__ >= 900
    cudaGridDependencySynchronize();
#endif

    // Prefetch c_top / c_mid rows (coalesced, L2-hot — just written)
    float ctT[EPW], ctU[EPW], cmT[EPW], cmU[EPW];
    #pragma unroll
    for (int j = 0; j < EPW; j++) {
        ctT[j] = g_ctop[ctop_off[j] + lane];
        ctU[j] = g_ctop[ctop_off[j] + lane + 32];
        cmT[j] = g_cmid[cmid_off[j] + lane];
        cmU[j] = g_cmid[cmid_off[j] + lane + 32];
    }

    // ---- Phase B: stage WbotP ----
    {
        const float4* src = (const float4*)g_WbotP;
        float4*       dst = (float4*)Wsh;
        #pragma unroll
        for (int i = 0; i < 2; i++) dst[i * 256 + tid] = src[i * 256 + tid];
    }
    __syncthreads();

    // ---- Phase C: 16 f-pair iters x 4 edges ----
    const ulonglong2* Wq = (const ulonglong2*)Wsh;
    const float* vb = vsh + (w * EPW) * CB;

    unsigned long long aT[EPW], aU[EPW];
    #pragma unroll
    for (int j = 0; j < EPW; j++) { aT[j] = 0ull; aU[j] = 0ull; }

    #pragma unroll
    for (int ip = 0; ip < NPB; ip++) {
        const ulonglong2 wq = Wq[ip * 32 + lane];
        #pragma unroll
        for (int j = 0; j < EPW; j++) {
            const unsigned long long vp =
                *(const unsigned long long*)(vb + j * CB + 2 * ip);  // broadcast
            FMA2(aT[j], vp, wq.x);
            FMA2(aU[j], vp, wq.y);
        }
    }

    // ---- Phase D: epilogue ----
    #pragma unroll
    for (int j = 0; j < EPW; j++) {
        float yT = __uint_as_float((unsigned)(aT[j] & 0xffffffffull))
                 + __uint_as_float((unsigned)(aT[j] >> 32))
                 + ctT[j] + cmT[j];
        float yU = __uint_as_float((unsigned)(aU[j] & 0xffffffffull))
                 + __uint_as_float((unsigned)(aU[j] >> 32))
                 + ctU[j] + cmU[j];
        yT = (yT > 0.0f) ? yT : NEG_SLOPE * yT;
        yU = (yU > 0.0f) ? yU : NEG_SLOPE * yU;

        float p = yT * waT + yU * waU;
        #pragma unroll
        for (int s = 16; s > 0; s >>= 1)
            p += __shfl_xor_sync(0xffffffffu, p, s);
        const float att = 1.0f / (1.0f + __expf(-(p + ba)));

        float* dst = out + cmid_off[j];   // (b*K + i2)*COUT
        atomicAdd(dst + lane,      att * yT);
        atomicAdd(dst + lane + 32, att * yU);
    }
}

// ---------------------------------------------------------------------------
extern "C" void kernel_launch(void* const* d_in, const int* in_sizes, int n_in,
                              void* d_out, int out_size)
{
    const float* sites1 = (const float*)d_in[0];
    const float* sites2 = (const float*)d_in[1];
    const float* bonds  = (const float*)d_in[2];
    const float* W_eq   = (const float*)d_in[3];
    const float* b_eq   = (const float*)d_in[4];
    const float* W_att  = (const float*)d_in[5];
    const float* b_att  = (const float*)d_in[6];
    // d_in[7] = idx2_oh (unused — collapsed analytically)
    const int*   idx1   = (const int*)d_in[8];
    const int*   idx2   = (const int*)d_in[9];
    // d_in[10], d_in[11] = perms1/perms2 (unused — permutations cancel)
    float* out = (float*)d_out;

    // prep: 64 CTAs x 256 threads (critical-path ~1us)
    {
        cudaLaunchConfig_t cfg = {};
        cfg.gridDim  = dim3(PREP_CTAS);
        cfg.blockDim = dim3(256);
        cfg.stream = 0;
        cudaLaunchKernelEx(&cfg, prep_kernel, sites1, sites2, W_eq, b_eq, out);
    }

    // main (PDL attr kept; benign if capture serializes)
    {
        cudaLaunchConfig_t cfg = {};
        cfg.gridDim  = dim3(GRID_M);
        cfg.blockDim = dim3(256);
        cfg.stream = 0;
        cudaLaunchAttribute at[1];
        at[0].id = cudaLaunchAttributeProgrammaticStreamSerialization;
        at[0].val.programmaticStreamSerializationAllowed = 1;
        cfg.attrs = at;
        cfg.numAttrs = 1;
        cudaLaunchKernelEx(&cfg, main_kernel, bonds, W_att, b_att,
                           idx1, idx2, out);
    }
}